// round 12
// baseline (speedup 1.0000x reference)
#include <cuda_runtime.h>
#include <math.h>

#define LEVELS 16
#define TABLE_SIZE 524288
#define HMASK (TABLE_SIZE - 1)
#define NPTS 1048576
#define PRIME 2654435761u
#define THREADS 256
#define GRID_B 512                        // 512 x 512 Morton buckets
#define NBUCKETS (GRID_B * GRID_B)        // 262144
#define SCAN_BLK 1024
#define NSCANBLK (NBUCKETS / SCAN_BLK)    // 256
#define SC_PER 4                          // points per scatter thread (MLP)
#define HI_PER 4                          // points per hist thread (MLP)
#define SSTR2 9                           // staging stride in float2 (8 + pad)

struct ResArr { float r[LEVELS]; };

typedef unsigned long long u64;

// Scratch (__device__ globals: the sanctioned no-allocation path)
__device__ int    d_hist[NBUCKETS];       // zero-init at load; scan re-zeros
__device__ int    d_done;                 // reset by scan's last block
__device__ int    d_offs[NBUCKETS];
__device__ int    d_bsum[NSCANBLK];
__device__ int    d_bbase[NSCANBLK];
__device__ float4 d_pts[NPTS];            // (x, y, bitcast(orig index), pad)

// ---- packed f32x2 helpers (sm_100+) ----
__device__ __forceinline__ u64 bcast2(float a) {
    u64 r; asm("mov.b64 %0, {%1, %1};" : "=l"(r) : "f"(a)); return r;
}
__device__ __forceinline__ u64 sub2(u64 a, u64 b) {
    u64 r; asm("sub.rn.f32x2 %0, %1, %2;" : "=l"(r) : "l"(a), "l"(b)); return r;
}
__device__ __forceinline__ u64 fma2(u64 a, u64 b, u64 c) {
    u64 r; asm("fma.rn.f32x2 %0, %1, %2, %3;" : "=l"(r) : "l"(a), "l"(b), "l"(c)); return r;
}
__device__ __forceinline__ void unpack2(u64 v, float& lo, float& hi) {
    asm("mov.b64 {%0, %1}, %2;" : "=f"(lo), "=f"(hi) : "l"(v));
}

__device__ __forceinline__ unsigned expand16(unsigned v) {
    v = (v | (v << 8)) & 0x00FF00FFu;
    v = (v | (v << 4)) & 0x0F0F0F0Fu;
    v = (v | (v << 2)) & 0x33333333u;
    v = (v | (v << 1)) & 0x55555555u;
    return v;
}
__device__ __forceinline__ unsigned bucket_of(float px, float py) {
    unsigned bx = (unsigned)(int)(px * (float)GRID_B);
    unsigned by = (unsigned)(int)(py * (float)GRID_B);
    bx = bx > (GRID_B - 1u) ? (GRID_B - 1u) : bx;
    by = by > (GRID_B - 1u) ? (GRID_B - 1u) : by;
    return expand16(bx) | (expand16(by) << 1);
}

// 4 points per thread via two coalesced float4 loads; batched atomics.
__global__ __launch_bounds__(THREADS)
void hist_kernel(const float4* __restrict__ x4) {
    const int QH = NPTS / 4;
    int t = blockIdx.x * blockDim.x + threadIdx.x;
    float4 a = x4[t];
    float4 b = x4[t + QH];
    atomicAdd(&d_hist[bucket_of(a.x, a.y)], 1);
    atomicAdd(&d_hist[bucket_of(a.z, a.w)], 1);
    atomicAdd(&d_hist[bucket_of(b.x, b.y)], 1);
    atomicAdd(&d_hist[bucket_of(b.z, b.w)], 1);
}

// Warp-shuffle exclusive scan per 1024-entry chunk; zeroes d_hist in place;
// the LAST block also scans the 256 chunk sums and resets d_done.
__global__ __launch_bounds__(SCAN_BLK)
void scan_kernel() {
    __shared__ int s_wsum[32];
    __shared__ int s_chunk;
    __shared__ bool is_last;
    int t    = threadIdx.x;
    int lane = t & 31;
    int wp   = t >> 5;
    int i    = blockIdx.x * SCAN_BLK + t;

    int v = d_hist[i];
    d_hist[i] = 0;                         // re-zero for next replay (exclusive)

    // warp inclusive scan
    int s = v;
#pragma unroll
    for (int o = 1; o < 32; o <<= 1) {
        int u = __shfl_up_sync(0xFFFFFFFFu, s, o);
        if (lane >= o) s += u;
    }
    if (lane == 31) s_wsum[wp] = s;
    __syncthreads();
    if (wp == 0) {                         // scan the 32 warp totals
        int ws = s_wsum[lane];
        int wi = ws;
#pragma unroll
        for (int o = 1; o < 32; o <<= 1) {
            int u = __shfl_up_sync(0xFFFFFFFFu, wi, o);
            if (lane >= o) wi += u;
        }
        s_wsum[lane] = wi - ws;            // exclusive warp base
        if (lane == 31) s_chunk = wi;      // chunk total
    }
    __syncthreads();
    int excl = s + s_wsum[wp] - v;         // exclusive within chunk
    d_offs[i] = excl;
    if (t == SCAN_BLK - 1) d_bsum[blockIdx.x] = s_chunk;

    __threadfence();
    if (t == 0) is_last = (atomicAdd(&d_done, 1) == NSCANBLK - 1);
    __syncthreads();
    if (is_last) {                         // block-uniform branch
        if (wp < NSCANBLK / 32) {          // 8 warps cover 256 sums
            int idx = wp * 32 + lane;
            int bv = d_bsum[idx];
            int bs = bv;
#pragma unroll
            for (int o = 1; o < 32; o <<= 1) {
                int u = __shfl_up_sync(0xFFFFFFFFu, bs, o);
                if (lane >= o) bs += u;
            }
            if (lane == 31) s_wsum[wp] = bs;   // per-warp totals of sums
            __syncwarp();
        }
        __syncthreads();
        if (wp == 0 && lane < NSCANBLK / 32) {
            int ws = s_wsum[lane];
            int wi = ws;
#pragma unroll
            for (int o = 1; o < 8; o <<= 1) {
                int u = __shfl_up_sync(0x000000FFu, wi, o);
                if (lane >= o) wi += u;
            }
            s_wsum[lane] = wi - ws;
        }
        __syncthreads();
        if (wp < NSCANBLK / 32) {
            int idx = wp * 32 + lane;
            int bv = d_bsum[idx];
            int bs = bv;
#pragma unroll
            for (int o = 1; o < 32; o <<= 1) {
                int u = __shfl_up_sync(0xFFFFFFFFu, bs, o);
                if (lane >= o) bs += u;
            }
            d_bbase[idx] = bs - bv + s_wsum[wp];
        }
        if (t == 0) d_done = 0;            // reset for next replay
    }
}

// 4 points per thread: batch the independent atomics, then the stores (MLP=4).
__global__ __launch_bounds__(THREADS)
void scatter_kernel(const float2* __restrict__ x) {
    const int Q = NPTS / SC_PER;
    int t = blockIdx.x * blockDim.x + threadIdx.x;
    float2   p[SC_PER];
    unsigned b[SC_PER];
    int      pos[SC_PER];
#pragma unroll
    for (int k = 0; k < SC_PER; ++k) {
        p[k] = x[t + k * Q];
        b[k] = bucket_of(p[k].x, p[k].y);
    }
#pragma unroll
    for (int k = 0; k < SC_PER; ++k)
        pos[k] = d_bbase[b[k] >> 10] + atomicAdd(&d_offs[b[k]], 1);
#pragma unroll
    for (int k = 0; k < SC_PER; ++k)
        d_pts[pos[k]] = make_float4(p[k].x, p[k].y,
                                    __int_as_float(t + k * Q), 0.0f);
}

__global__ __launch_bounds__(THREADS, 8)
void hashenc_kernel(const float2* __restrict__ tables,
                    float* __restrict__ out,
                    ResArr res)
{
    __shared__ float2 s2[THREADS * SSTR2];    // 18.4 KB
    __shared__ int    s_idx[THREADS];         // 1 KB
    int tid  = threadIdx.x;
    int lane = tid & 31;
    int w    = tid >> 5;
    int j    = blockIdx.x * THREADS + tid;

    float4 pk = d_pts[j];
    float px = pk.x, py = pk.y;
    s_idx[tid] = __float_as_int(pk.z);

    const u64* tu = reinterpret_cast<const u64*>(tables);

#pragma unroll
    for (int ph = 0; ph < 2; ++ph) {
        if (ph) __syncthreads();              // writes done before restage
        float a0e = 0.0f, a1e = 0.0f;
#pragma unroll
        for (int li = 0; li < 8; ++li) {
            const int l = ph * 8 + li;
            const u64* t = tu + (size_t)l * TABLE_SIZE;
            float r  = res.r[l];
            float sx = px * r;
            float sy = py * r;
            float gxf = floorf(sx);
            float gyf = floorf(sy);
            float fx = sx - gxf;
            float fy = sy - gyf;

            unsigned gx = (unsigned)(int)gxf;
            unsigned gy = (unsigned)(int)gyf;
            unsigned hy0 = gy * PRIME;
            unsigned hy1 = hy0 + PRIME;

            u64 F00 = __ldg(t + (( gx        ^ hy0) & HMASK));
            u64 F10 = __ldg(t + (((gx + 1u)  ^ hy0) & HMASK));
            u64 F01 = __ldg(t + (( gx        ^ hy1) & HMASK));
            u64 F11 = __ldg(t + (((gx + 1u)  ^ hy1) & HMASK));

            // A = fy*(fx*F00 + (1-fx)*F10) + (1-fy)*(fx*F01 + (1-fx)*F11)
            u64 FX = bcast2(fx);
            u64 FY = bcast2(fy);
            u64 I0 = fma2(FX, sub2(F00, F10), F10);
            u64 I1 = fma2(FX, sub2(F01, F11), F11);
            u64 A  = fma2(FY, sub2(I0, I1), I1);

            float a0, a1;
            unpack2(A, a0, a1);

            if (li & 1) {                     // STS.64 per level-pair
                s2[tid * SSTR2 + (li >> 1)]     = make_float2(a0e, a0);
                s2[tid * SSTR2 + 4 + (li >> 1)] = make_float2(a1e, a1);
            } else { a0e = a0; a1e = a1; }
        }
        __syncthreads();

        // Write loop: lane handles one float2 (two adjacent out columns);
        // warp covers 4 rows x 8 slots per iteration -> 8 iterations/phase.
        int c    = lane & 7;
        int rsub = lane >> 3;
        int col  = (c < 4) ? (ph * 8 + 2 * c) : (8 + ph * 8 + 2 * c);
        for (int k = w; k < THREADS / 4; k += THREADS / 32) {
            int rrow = 4 * k + rsub;
            int nn = s_idx[rrow];             // broadcast LDS
            float2 v = s2[rrow * SSTR2 + c];
            *reinterpret_cast<float2*>(&out[(size_t)nn * 32 + col]) = v;
        }
    }
}

extern "C" void kernel_launch(void* const* d_in, const int* in_sizes, int n_in,
                              void* d_out, int out_size)
{
    // Exact float64 replication of the reference _RESOLUTIONS computation.
    ResArr res;
    double b = exp((log(512.0) - log(16.0)) / 15.0);
    for (int l = 0; l < LEVELS; ++l) {
        double pw;
        if (l == 0)      pw = 1.0;
        else if (l == 1) pw = b;
        else             pw = pow(b, (double)l);
        res.r[l] = (float)floor(16.0 * pw);
    }

    const float2* x      = (const float2*)d_in[0];
    const float2* tables = (const float2*)d_in[1];
    float*        out    = (float*)d_out;

    hist_kernel<<<NPTS / HI_PER / THREADS, THREADS>>>((const float4*)x);
    scan_kernel<<<NSCANBLK, SCAN_BLK>>>();
    scatter_kernel<<<NPTS / SC_PER / THREADS, THREADS>>>(x);
    hashenc_kernel<<<NPTS / THREADS, THREADS>>>(tables, out, res);
}

// round 13
// speedup vs baseline: 1.0234x; 1.0234x over previous
#include <cuda_runtime.h>
#include <math.h>

#define LEVELS 16
#define TABLE_SIZE 524288
#define HMASK (TABLE_SIZE - 1)
#define NPTS 1048576
#define PRIME 2654435761u
#define THREADS 256
#define GRID_B 512                        // 512 x 512 Morton buckets
#define NBUCKETS (GRID_B * GRID_B)        // 262144
#define SCAN_BLK 1024
#define NSCANBLK (NBUCKETS / SCAN_BLK)    // 256
#define SC_PER 8                          // points per scatter thread (MLP)
#define HI_PER 8                          // points per hist thread (MLP)
#define SSTR2 9                           // staging stride in float2 (8 + pad)

struct ResArr { float r[LEVELS]; };

typedef unsigned long long u64;

// Scratch (__device__ globals: the sanctioned no-allocation path)
__device__ int    d_hist[NBUCKETS];       // zero-init at load; gather tail re-zeros
__device__ int    d_done;                 // reset by gather tail
__device__ int    d_offs[NBUCKETS];
__device__ int    d_bsum[NSCANBLK];
__device__ int    d_bbase[NSCANBLK];
__device__ float4 d_pts[NPTS];            // (x, y, bitcast(orig index), pad)

// ---- packed f32x2 helpers (sm_100+) ----
__device__ __forceinline__ u64 bcast2(float a) {
    u64 r; asm("mov.b64 %0, {%1, %1};" : "=l"(r) : "f"(a)); return r;
}
__device__ __forceinline__ u64 sub2(u64 a, u64 b) {
    u64 r; asm("sub.rn.f32x2 %0, %1, %2;" : "=l"(r) : "l"(a), "l"(b)); return r;
}
__device__ __forceinline__ u64 fma2(u64 a, u64 b, u64 c) {
    u64 r; asm("fma.rn.f32x2 %0, %1, %2, %3;" : "=l"(r) : "l"(a), "l"(b), "l"(c)); return r;
}
__device__ __forceinline__ void unpack2(u64 v, float& lo, float& hi) {
    asm("mov.b64 {%0, %1}, %2;" : "=f"(lo), "=f"(hi) : "l"(v));
}

__device__ __forceinline__ unsigned expand16(unsigned v) {
    v = (v | (v << 8)) & 0x00FF00FFu;
    v = (v | (v << 4)) & 0x0F0F0F0Fu;
    v = (v | (v << 2)) & 0x33333333u;
    v = (v | (v << 1)) & 0x55555555u;
    return v;
}
__device__ __forceinline__ unsigned bucket_of(float px, float py) {
    unsigned bx = (unsigned)(int)(px * (float)GRID_B);
    unsigned by = (unsigned)(int)(py * (float)GRID_B);
    bx = bx > (GRID_B - 1u) ? (GRID_B - 1u) : bx;
    by = by > (GRID_B - 1u) ? (GRID_B - 1u) : by;
    return expand16(bx) | (expand16(by) << 1);
}

// 8 points per thread via four coalesced float4 loads; batched atomics.
__global__ __launch_bounds__(THREADS)
void hist_kernel(const float4* __restrict__ x4) {
    const int QH = NPTS / 8;              // float4 count / 4 quarters
    int t = blockIdx.x * blockDim.x + threadIdx.x;
    float4 q[4];
#pragma unroll
    for (int k = 0; k < 4; ++k) q[k] = x4[t + k * QH];
#pragma unroll
    for (int k = 0; k < 4; ++k) {
        atomicAdd(&d_hist[bucket_of(q[k].x, q[k].y)], 1);
        atomicAdd(&d_hist[bucket_of(q[k].z, q[k].w)], 1);
    }
}

// Warp-shuffle exclusive scan per 1024-entry chunk;
// the LAST block also scans the 256 chunk sums.
__global__ __launch_bounds__(SCAN_BLK)
void scan_kernel() {
    __shared__ int s_wsum[32];
    __shared__ int s_chunk;
    __shared__ bool is_last;
    int t    = threadIdx.x;
    int lane = t & 31;
    int wp   = t >> 5;
    int i    = blockIdx.x * SCAN_BLK + t;

    int v = d_hist[i];

    // warp inclusive scan
    int s = v;
#pragma unroll
    for (int o = 1; o < 32; o <<= 1) {
        int u = __shfl_up_sync(0xFFFFFFFFu, s, o);
        if (lane >= o) s += u;
    }
    if (lane == 31) s_wsum[wp] = s;
    __syncthreads();
    if (wp == 0) {                         // scan the 32 warp totals
        int ws = s_wsum[lane];
        int wi = ws;
#pragma unroll
        for (int o = 1; o < 32; o <<= 1) {
            int u = __shfl_up_sync(0xFFFFFFFFu, wi, o);
            if (lane >= o) wi += u;
        }
        s_wsum[lane] = wi - ws;            // exclusive warp base
        if (lane == 31) s_chunk = wi;      // chunk total
    }
    __syncthreads();
    d_offs[i] = s + s_wsum[wp] - v;        // exclusive within chunk
    if (t == SCAN_BLK - 1) d_bsum[blockIdx.x] = s_chunk;

    __threadfence();
    if (t == 0) is_last = (atomicAdd(&d_done, 1) == NSCANBLK - 1);
    __syncthreads();
    if (is_last) {                         // block-uniform branch
        if (wp < NSCANBLK / 32) {          // 8 warps cover 256 sums
            int idx = wp * 32 + lane;
            int bv = d_bsum[idx];
            int bs = bv;
#pragma unroll
            for (int o = 1; o < 32; o <<= 1) {
                int u = __shfl_up_sync(0xFFFFFFFFu, bs, o);
                if (lane >= o) bs += u;
            }
            if (lane == 31) s_wsum[wp] = bs;   // per-warp totals of sums
        }
        __syncthreads();
        if (wp == 0 && lane < NSCANBLK / 32) {
            int ws = s_wsum[lane];
            int wi = ws;
#pragma unroll
            for (int o = 1; o < 8; o <<= 1) {
                int u = __shfl_up_sync(0x000000FFu, wi, o);
                if (lane >= o) wi += u;
            }
            s_wsum[lane] = wi - ws;
        }
        __syncthreads();
        if (wp < NSCANBLK / 32) {
            int idx = wp * 32 + lane;
            int bv = d_bsum[idx];
            int bs = bv;
#pragma unroll
            for (int o = 1; o < 32; o <<= 1) {
                int u = __shfl_up_sync(0xFFFFFFFFu, bs, o);
                if (lane >= o) bs += u;
            }
            d_bbase[idx] = bs - bv + s_wsum[wp];
        }
    }
}

// 8 points per thread: batch the independent atomics, then the stores (MLP=8).
__global__ __launch_bounds__(THREADS)
void scatter_kernel(const float2* __restrict__ x) {
    const int Q = NPTS / SC_PER;
    int t = blockIdx.x * blockDim.x + threadIdx.x;
    float2   p[SC_PER];
    unsigned b[SC_PER];
    int      pos[SC_PER];
#pragma unroll
    for (int k = 0; k < SC_PER; ++k) {
        p[k] = x[t + k * Q];
        b[k] = bucket_of(p[k].x, p[k].y);
    }
#pragma unroll
    for (int k = 0; k < SC_PER; ++k)
        pos[k] = d_bbase[b[k] >> 10] + atomicAdd(&d_offs[b[k]], 1);
#pragma unroll
    for (int k = 0; k < SC_PER; ++k)
        d_pts[pos[k]] = make_float4(p[k].x, p[k].y,
                                    __int_as_float(t + k * Q), 0.0f);
}

__global__ __launch_bounds__(THREADS, 8)
void hashenc_kernel(const float2* __restrict__ tables,
                    float* __restrict__ out,
                    ResArr res)
{
    __shared__ float2 s2[THREADS * SSTR2];    // 18.4 KB
    __shared__ int    s_idx[THREADS];         // 1 KB
    int tid  = threadIdx.x;
    int lane = tid & 31;
    int w    = tid >> 5;
    int j    = blockIdx.x * THREADS + tid;

    float4 pk = d_pts[j];
    float px = pk.x, py = pk.y;
    s_idx[tid] = __float_as_int(pk.z);

    const u64* tu = reinterpret_cast<const u64*>(tables);

#pragma unroll
    for (int ph = 0; ph < 2; ++ph) {
        if (ph) __syncthreads();              // writes done before restage
        float a0e = 0.0f, a1e = 0.0f;
#pragma unroll
        for (int li = 0; li < 8; ++li) {
            const int l = ph * 8 + li;
            const u64* t = tu + (size_t)l * TABLE_SIZE;
            float r  = res.r[l];
            float sx = px * r;
            float sy = py * r;
            float gxf = floorf(sx);
            float gyf = floorf(sy);
            float fx = sx - gxf;
            float fy = sy - gyf;

            unsigned gx = (unsigned)(int)gxf;
            unsigned gy = (unsigned)(int)gyf;
            unsigned hy0 = gy * PRIME;
            unsigned hy1 = hy0 + PRIME;

            u64 F00 = __ldg(t + (( gx        ^ hy0) & HMASK));
            u64 F10 = __ldg(t + (((gx + 1u)  ^ hy0) & HMASK));
            u64 F01 = __ldg(t + (( gx        ^ hy1) & HMASK));
            u64 F11 = __ldg(t + (((gx + 1u)  ^ hy1) & HMASK));

            // A = fy*(fx*F00 + (1-fx)*F10) + (1-fy)*(fx*F01 + (1-fx)*F11)
            u64 FX = bcast2(fx);
            u64 FY = bcast2(fy);
            u64 I0 = fma2(FX, sub2(F00, F10), F10);
            u64 I1 = fma2(FX, sub2(F01, F11), F11);
            u64 A  = fma2(FY, sub2(I0, I1), I1);

            float a0, a1;
            unpack2(A, a0, a1);

            if (li & 1) {                     // STS.64 per level-pair
                s2[tid * SSTR2 + (li >> 1)]     = make_float2(a0e, a0);
                s2[tid * SSTR2 + 4 + (li >> 1)] = make_float2(a1e, a1);
            } else { a0e = a0; a1e = a1; }
        }
        __syncthreads();

        // Write loop: lane handles one float2 (two adjacent out columns);
        // warp covers 4 rows x 8 slots per iteration -> 8 iterations/phase.
        int c    = lane & 7;
        int rsub = lane >> 3;
        int col  = (c < 4) ? (ph * 8 + 2 * c) : (8 + ph * 8 + 2 * c);
        for (int k = w; k < THREADS / 4; k += THREADS / 32) {
            int rrow = 4 * k + rsub;
            int nn = s_idx[rrow];             // broadcast LDS
            float2 v = s2[rrow * SSTR2 + c];
            *reinterpret_cast<float2*>(&out[(size_t)nn * 32 + col]) = v;
        }
    }

    // Tail: zero the histogram (and d_done) for the next call — effectively
    // free here (overlaps kernel drain). Globals are zero-initialized at
    // module load, so the first call is also correct.
    int g = blockIdx.x * THREADS + tid;
    if (g < NBUCKETS) d_hist[g] = 0;
    if (g == 0) d_done = 0;
}

extern "C" void kernel_launch(void* const* d_in, const int* in_sizes, int n_in,
                              void* d_out, int out_size)
{
    // Exact float64 replication of the reference _RESOLUTIONS computation.
    ResArr res;
    double b = exp((log(512.0) - log(16.0)) / 15.0);
    for (int l = 0; l < LEVELS; ++l) {
        double pw;
        if (l == 0)      pw = 1.0;
        else if (l == 1) pw = b;
        else             pw = pow(b, (double)l);
        res.r[l] = (float)floor(16.0 * pw);
    }

    const float2* x      = (const float2*)d_in[0];
    const float2* tables = (const float2*)d_in[1];
    float*        out    = (float*)d_out;

    hist_kernel<<<NPTS / HI_PER / THREADS, THREADS>>>((const float4*)x);
    scan_kernel<<<NSCANBLK, SCAN_BLK>>>();
    scatter_kernel<<<NPTS / SC_PER / THREADS, THREADS>>>(x);
    hashenc_kernel<<<NPTS / THREADS, THREADS>>>(tables, out, res);
}